// round 4
// baseline (speedup 1.0000x reference)
#include <cuda_runtime.h>
#include <math.h>
#include <stdint.h>

// Problem constants
#define Nn   256
#define Ll   384
#define Dd   256
#define DP   128
#define Hh   8
#define DHh  32
#define NL   (Nn*Ll)      // 98304 rows
#define LLp  (Ll*Ll)      // 147456
#define EPSF 1e-5f
#define SCALE 0.17677669529663687f  // 1/sqrt(32)

// ---------------- scratch (device globals; no allocation allowed) ----------------
__device__ float g_m   [NL*Dd];   // layernormed msa
__device__ float g_q   [NL*Dd];   // q projection (seq-weighted in epilogue)
__device__ float g_k   [NL*Dd];   // k projection (scaled)
__device__ float g_v   [NL*Dd];   // v projection
__device__ float g_g   [NL*Dd];   // gate
__device__ float g_o   [NL*Dd];   // ksw temp, later attention output
__device__ float g_qsw [Ll*Dd];   // seq-weight queries
__device__ float g_sw  [NL*Hh];   // sw logits -> seq weights
__device__ float g_logits[Hh*LLp]; // logits(+bias) -> attn
__device__ float g_bias  [Hh*LLp]; // pair bias

// ---------------- LayerNorm over D=256 (one row per block) ----------------
__global__ void ln_msa_kernel(const float* __restrict__ x, const float* __restrict__ g,
                              const float* __restrict__ b, float* __restrict__ out) {
    __shared__ float s1[8], s2[8];
    __shared__ float mu_s, rs_s;
    int row = blockIdx.x;
    int t = threadIdx.x;
    float v = x[(size_t)row*Dd + t];
    float s = v, q = v*v;
    #pragma unroll
    for (int o = 16; o; o >>= 1) {
        s += __shfl_down_sync(0xffffffffu, s, o);
        q += __shfl_down_sync(0xffffffffu, q, o);
    }
    int lane = t & 31, w = t >> 5;
    if (!lane) { s1[w] = s; s2[w] = q; }
    __syncthreads();
    if (w == 0) {
        float ss = (lane < 8) ? s1[lane] : 0.f;
        float qq = (lane < 8) ? s2[lane] : 0.f;
        #pragma unroll
        for (int o = 16; o; o >>= 1) {
            ss += __shfl_down_sync(0xffffffffu, ss, o);
            qq += __shfl_down_sync(0xffffffffu, qq, o);
        }
        if (!lane) {
            float mu = ss * (1.0f/Dd);
            float var = qq * (1.0f/Dd) - mu*mu;
            mu_s = mu;
            rs_s = rsqrtf(var + EPSF);
        }
    }
    __syncthreads();
    out[(size_t)row*Dd + t] = (v - mu_s) * rs_s * g[t] + b[t];
}

// ---------------- Generic GEMM: C[Mx256] = act((A(*A2) @ W + bias)*scale [*sw]) ----------------
// A: Mx256 row-major, W: 256x256 row-major. BM=BN=128, BK=16, 256 threads, 8x8 microtile.
// SW: multiply output by swp[row*H + (col>>5)] (per-row, per-head seq weight).
template<bool GATE, bool SIG, bool BIAS, bool SW>
__global__ void __launch_bounds__(256) gemm256_kernel(
        const float* __restrict__ A, const float* __restrict__ A2,
        const float* __restrict__ W, const float* __restrict__ bias,
        const float* __restrict__ swp,
        float scale, float* __restrict__ C) {
    __shared__ float As[16][132];
    __shared__ float Bs[16][132];
    int tid = threadIdx.x;
    int tx = tid & 15, ty = tid >> 4;
    int m0 = blockIdx.y * 128, n0 = blockIdx.x * 128;

    float acc[8][8];
    #pragma unroll
    for (int r = 0; r < 8; r++)
        #pragma unroll
        for (int c = 0; c < 8; c++) acc[r][c] = 0.f;

    for (int kt = 0; kt < 16; kt++) {
        int k0 = kt * 16;
        // load A tile 128x16 (transposed into As[k][m])
        #pragma unroll
        for (int u = 0; u < 2; u++) {
            int f = tid*2 + u;
            int row = f >> 2, c4 = f & 3;
            const float* ap = A + (size_t)(m0+row)*Dd + k0 + c4*4;
            float4 v = *(const float4*)ap;
            if (GATE) {
                const float* gp = A2 + (size_t)(m0+row)*Dd + k0 + c4*4;
                float4 gt = *(const float4*)gp;
                v.x *= gt.x; v.y *= gt.y; v.z *= gt.z; v.w *= gt.w;
            }
            As[c4*4+0][row] = v.x;
            As[c4*4+1][row] = v.y;
            As[c4*4+2][row] = v.z;
            As[c4*4+3][row] = v.w;
        }
        // load W tile 16x128
        #pragma unroll
        for (int u = 0; u < 2; u++) {
            int f = tid*2 + u;
            int kr = f >> 5, c4 = f & 31;
            float4 v = *(const float4*)(W + (size_t)(k0+kr)*Dd + n0 + c4*4);
            *(float4*)&Bs[kr][c4*4] = v;
        }
        __syncthreads();
        #pragma unroll
        for (int kk = 0; kk < 16; kk++) {
            float rA[8], rB[8];
            *(float4*)&rA[0] = *(float4*)&As[kk][ty*8];
            *(float4*)&rA[4] = *(float4*)&As[kk][ty*8+4];
            *(float4*)&rB[0] = *(float4*)&Bs[kk][tx*8];
            *(float4*)&rB[4] = *(float4*)&Bs[kk][tx*8+4];
            #pragma unroll
            for (int r = 0; r < 8; r++)
                #pragma unroll
                for (int c = 0; c < 8; c++) acc[r][c] += rA[r]*rB[c];
        }
        __syncthreads();
    }
    float bn[8];
    #pragma unroll
    for (int c = 0; c < 8; c++) bn[c] = BIAS ? bias[n0 + tx*8 + c] : 0.f;
    #pragma unroll
    for (int r = 0; r < 8; r++) {
        int row = m0 + ty*8 + r;
        float swv0 = 0.f, swv1 = 0.f;
        if (SW) {
            // 8 consecutive output cols tx*8..tx*8+7 span at most 2 heads (head = col>>5)
            swv0 = swp[(size_t)row*Hh + ((n0 + tx*8) >> 5)];
            swv1 = swp[(size_t)row*Hh + ((n0 + tx*8 + 7) >> 5)];
        }
        float outv[8];
        #pragma unroll
        for (int c = 0; c < 8; c++) {
            float val = (acc[r][c] + bn[c]) * scale;
            if (SIG) val = 1.f / (1.f + expf(-val));
            if (SW)  val *= (((n0 + tx*8 + c) >> 5) == ((n0 + tx*8) >> 5)) ? swv0 : swv1;
            outv[c] = val;
        }
        *(float4*)(C + (size_t)row*Dd + n0 + tx*8)     = *(float4*)&outv[0];
        *(float4*)(C + (size_t)row*Dd + n0 + tx*8 + 4) = *(float4*)&outv[4];
    }
}

// ---------------- sw_logits[n,i,h] = dot(qsw[i,h,:], ksw[n,i,h,:]) ----------------
__global__ void swlogits_kernel(const float* __restrict__ qsw, const float* __restrict__ ksw,
                                float* __restrict__ swout) {
    int row = blockIdx.x;            // n*L + i
    int i = row % Ll;
    int t = threadIdx.x;             // 256: warp w = head
    float v = qsw[i*Dd + t] * ksw[(size_t)row*Dd + t];
    #pragma unroll
    for (int o = 16; o; o >>= 1) v += __shfl_down_sync(0xffffffffu, v, o);
    if ((t & 31) == 0) swout[row*Hh + (t >> 5)] = v;
}

// ---------------- softmax over n (256) for each (i,h) ----------------
__global__ void swsoftmax_kernel(float* __restrict__ sw) {
    __shared__ float sm[8];
    __shared__ float red;
    int ih = blockIdx.x;             // i*H + h
    int n = threadIdx.x;             // 256
    int lane = n & 31, w = n >> 5;
    float v = sw[(size_t)n*(Ll*Hh) + ih];
    float mx = v;
    #pragma unroll
    for (int o = 16; o; o >>= 1) mx = fmaxf(mx, __shfl_down_sync(0xffffffffu, mx, o));
    if (!lane) sm[w] = mx;
    __syncthreads();
    if (w == 0) {
        float x = (lane < 8) ? sm[lane] : -3.4e38f;
        #pragma unroll
        for (int o = 16; o; o >>= 1) x = fmaxf(x, __shfl_down_sync(0xffffffffu, x, o));
        if (!lane) red = x;
    }
    __syncthreads();
    mx = red;
    float e = expf(v - mx);
    float s = e;
    #pragma unroll
    for (int o = 16; o; o >>= 1) s += __shfl_down_sync(0xffffffffu, s, o);
    __syncthreads();
    if (!lane) sm[w] = s;
    __syncthreads();
    if (w == 0) {
        float x = (lane < 8) ? sm[lane] : 0.f;
        #pragma unroll
        for (int o = 16; o; o >>= 1) x += __shfl_down_sync(0xffffffffu, x, o);
        if (!lane) red = x;
    }
    __syncthreads();
    sw[(size_t)n*(Ll*Hh) + ih] = e / red;
}

// ---------------- pair bias: LN(pair row) @ Wb -> bias[h][i][j] ----------------
__global__ void pairbias_kernel(const float* __restrict__ pair, const float* __restrict__ g,
                                const float* __restrict__ b, const float* __restrict__ Wb,
                                float* __restrict__ bias) {
    __shared__ float s1[4], s2[4];
    __shared__ float hp[4][8];
    int ij = blockIdx.x;             // i*L + j
    int t = threadIdx.x;             // 128
    int lane = t & 31, w = t >> 5;
    float v = pair[(size_t)ij*DP + t];
    float s = v, q = v*v;
    #pragma unroll
    for (int o = 16; o; o >>= 1) {
        s += __shfl_down_sync(0xffffffffu, s, o);
        q += __shfl_down_sync(0xffffffffu, q, o);
    }
    if (!lane) { s1[w] = s; s2[w] = q; }
    __syncthreads();
    if (w == 0) {
        float ss = (lane < 4) ? s1[lane] : 0.f;
        float qq = (lane < 4) ? s2[lane] : 0.f;
        #pragma unroll
        for (int o = 16; o; o >>= 1) {
            ss += __shfl_down_sync(0xffffffffu, ss, o);
            qq += __shfl_down_sync(0xffffffffu, qq, o);
        }
        if (!lane) { s1[0] = ss; s2[0] = qq; }
    }
    __syncthreads();
    float mu = s1[0] * (1.0f/DP);
    float var = s2[0] * (1.0f/DP) - mu*mu;
    float ln = (v - mu) * rsqrtf(var + EPSF) * g[t] + b[t];
    float p[8];
    #pragma unroll
    for (int h = 0; h < 8; h++) p[h] = ln * Wb[t*Hh + h];
    #pragma unroll
    for (int h = 0; h < 8; h++)
        #pragma unroll
        for (int o = 16; o; o >>= 1) p[h] += __shfl_down_sync(0xffffffffu, p[h], o);
    if (!lane) {
        #pragma unroll
        for (int h = 0; h < 8; h++) hp[w][h] = p[h];
    }
    __syncthreads();
    if (t < 8) {
        float x = hp[0][t] + hp[1][t] + hp[2][t] + hp[3][t];
        bias[(size_t)t*LLp + ij] = x;
    }
}

// ---------------- logits[h][i][j] = sum_{n,d} qw[n,i,h,d] * k[n,j,h,d] + bias[h][i][j] ----------------
// grid (6, 6, 8): 64x64 tile over (i, j), K loop over n (d inside)
__global__ void __launch_bounds__(256) logits_kernel(const float* __restrict__ q,
        const float* __restrict__ kk, const float* __restrict__ bias,
        float* __restrict__ out) {
    __shared__ float As[32][68];   // As[d][i]
    __shared__ float Bs[32][68];   // Bs[d][j]
    int h = blockIdx.z;
    int i0 = blockIdx.y * 64, j0 = blockIdx.x * 64;
    int tid = threadIdx.x, tx = tid & 15, ty = tid >> 4;
    float acc[4][4];
    #pragma unroll
    for (int r = 0; r < 4; r++)
        #pragma unroll
        for (int c = 0; c < 4; c++) acc[r][c] = 0.f;

    for (int n = 0; n < Nn; n++) {
        #pragma unroll
        for (int u = 0; u < 2; u++) {
            int f = tid*2 + u;
            int irow = f >> 3, dc = f & 7;
            float4 a = *(const float4*)(q  + (size_t)(n*Ll + i0 + irow)*Dd + h*DHh + dc*4);
            As[dc*4+0][irow] = a.x; As[dc*4+1][irow] = a.y;
            As[dc*4+2][irow] = a.z; As[dc*4+3][irow] = a.w;
            float4 bv = *(const float4*)(kk + (size_t)(n*Ll + j0 + irow)*Dd + h*DHh + dc*4);
            Bs[dc*4+0][irow] = bv.x; Bs[dc*4+1][irow] = bv.y;
            Bs[dc*4+2][irow] = bv.z; Bs[dc*4+3][irow] = bv.w;
        }
        __syncthreads();
        #pragma unroll
        for (int d = 0; d < 32; d++) {
            float rA[4], rB[4];
            *(float4*)rA = *(float4*)&As[d][ty*4];
            *(float4*)rB = *(float4*)&Bs[d][tx*4];
            #pragma unroll
            for (int r = 0; r < 4; r++)
                #pragma unroll
                for (int c = 0; c < 4; c++) acc[r][c] += rA[r]*rB[c];
        }
        __syncthreads();
    }
    #pragma unroll
    for (int r = 0; r < 4; r++) {
        size_t idx = (size_t)h*LLp + (size_t)(i0 + ty*4 + r)*Ll + j0 + tx*4;
        float4 bb = *(const float4*)(bias + idx);
        float4 o;
        o.x = acc[r][0] + bb.x; o.y = acc[r][1] + bb.y;
        o.z = acc[r][2] + bb.z; o.w = acc[r][3] + bb.w;
        *(float4*)(out + idx) = o;
    }
}

// ---------------- softmax over j (384) for each (h, i) ----------------
__global__ void attnsoftmax_kernel(float* __restrict__ logits) {
    __shared__ float sm[12];
    __shared__ float red;
    int hi = blockIdx.x;             // h*L + i
    size_t base = (size_t)hi * Ll;   // == h*LL + i*L
    int j = threadIdx.x;             // 384 threads, 12 warps
    int lane = j & 31, w = j >> 5;
    float v = logits[base + j];
    float mx = v;
    #pragma unroll
    for (int o = 16; o; o >>= 1) mx = fmaxf(mx, __shfl_down_sync(0xffffffffu, mx, o));
    if (!lane) sm[w] = mx;
    __syncthreads();
    if (w == 0) {
        float x = (lane < 12) ? sm[lane] : -3.4e38f;
        #pragma unroll
        for (int o = 16; o; o >>= 1) x = fmaxf(x, __shfl_down_sync(0xffffffffu, x, o));
        if (!lane) red = x;
    }
    __syncthreads();
    mx = red;
    float e = expf(v - mx);
    float s = e;
    #pragma unroll
    for (int o = 16; o; o >>= 1) s += __shfl_down_sync(0xffffffffu, s, o);
    __syncthreads();
    if (!lane) sm[w] = s;
    __syncthreads();
    if (w == 0) {
        float x = (lane < 12) ? sm[lane] : 0.f;
        #pragma unroll
        for (int o = 16; o; o >>= 1) x += __shfl_down_sync(0xffffffffu, x, o);
        if (!lane) red = x;
    }
    __syncthreads();
    logits[base + j] = e / red;
}

// ---------------- out[(n,i),(h,d)] = sum_j attn[h][i][j] * v[(n,j),(h,d)] ----------------
// grid (128, 6, 8): 64 (i) x 64 (c = n_local*32+d) tile, K loop over j
__global__ void __launch_bounds__(256) outgemm_kernel(const float* __restrict__ attn,
        const float* __restrict__ v, float* __restrict__ out) {
    __shared__ float As[32][68];   // As[j][i]
    __shared__ float Bs[32][68];   // Bs[j][c]
    int h = blockIdx.z;
    int i0 = blockIdx.y * 64, c0 = blockIdx.x * 64;
    int tid = threadIdx.x, tx = tid & 15, ty = tid >> 4;
    float acc[4][4];
    #pragma unroll
    for (int r = 0; r < 4; r++)
        #pragma unroll
        for (int c = 0; c < 4; c++) acc[r][c] = 0.f;

    for (int jt = 0; jt < 12; jt++) {
        int j0 = jt * 32;
        #pragma unroll
        for (int u = 0; u < 2; u++) {
            int f = tid*2 + u;
            {   // attn tile: 64 i x 32 j
                int irow = f >> 3, jc = f & 7;
                float4 a = *(const float4*)(attn + (size_t)h*LLp + (size_t)(i0 + irow)*Ll + j0 + jc*4);
                As[jc*4+0][irow] = a.x; As[jc*4+1][irow] = a.y;
                As[jc*4+2][irow] = a.z; As[jc*4+3][irow] = a.w;
            }
            {   // v tile: 32 j x 64 c
                int jrow = f >> 4, cc = f & 15;
                int cg = c0 + cc*4;
                int nn = cg >> 5, dd = cg & 31;
                float4 bv = *(const float4*)(v + (size_t)(nn*Ll + j0 + jrow)*Dd + h*DHh + dd);
                *(float4*)&Bs[jrow][cc*4] = bv;
            }
        }
        __syncthreads();
        #pragma unroll
        for (int j = 0; j < 32; j++) {
            float rA[4], rB[4];
            *(float4*)rA = *(float4*)&As[j][ty*4];
            *(float4*)rB = *(float4*)&Bs[j][tx*4];
            #pragma unroll
            for (int r = 0; r < 4; r++)
                #pragma unroll
                for (int c = 0; c < 4; c++) acc[r][c] += rA[r]*rB[c];
        }
        __syncthreads();
    }
    #pragma unroll
    for (int r = 0; r < 4; r++) {
        int i = i0 + ty*4 + r;
        int cg = c0 + tx*4;
        int nn = cg >> 5, dd = cg & 31;
        float4 o;
        o.x = acc[r][0]; o.y = acc[r][1]; o.z = acc[r][2]; o.w = acc[r][3];
        *(float4*)(out + (size_t)(nn*Ll + i)*Dd + h*DHh + dd) = o;
    }
}

// ---------------- host launch ----------------
extern "C" void kernel_launch(void* const* d_in, const int* in_sizes, int n_in,
                              void* d_out, int out_size) {
    const float* msa       = (const float*)d_in[0];
    const float* pair      = (const float*)d_in[1];
    const float* ln_msa_g  = (const float*)d_in[2];
    const float* ln_msa_b  = (const float*)d_in[3];
    const float* ln_pair_g = (const float*)d_in[4];
    const float* ln_pair_b = (const float*)d_in[5];
    const float* Wq_sw     = (const float*)d_in[6];
    const float* bq_sw     = (const float*)d_in[7];
    const float* Wk_sw     = (const float*)d_in[8];
    const float* bk_sw     = (const float*)d_in[9];
    const float* Wq        = (const float*)d_in[10];
    const float* Wk        = (const float*)d_in[11];
    const float* Wv        = (const float*)d_in[12];
    const float* Wb        = (const float*)d_in[13];
    const float* Wg        = (const float*)d_in[14];
    const float* bg        = (const float*)d_in[15];
    const float* Wo        = (const float*)d_in[16];
    const float* bo        = (const float*)d_in[17];
    float* out = (float*)d_out;

    float *m_, *q_, *k_, *v_, *gg_, *o_, *qsw_, *sw_, *lg_, *bi_;
    cudaGetSymbolAddress((void**)&m_,   g_m);
    cudaGetSymbolAddress((void**)&q_,   g_q);
    cudaGetSymbolAddress((void**)&k_,   g_k);
    cudaGetSymbolAddress((void**)&v_,   g_v);
    cudaGetSymbolAddress((void**)&gg_,  g_g);
    cudaGetSymbolAddress((void**)&o_,   g_o);
    cudaGetSymbolAddress((void**)&qsw_, g_qsw);
    cudaGetSymbolAddress((void**)&sw_,  g_sw);
    cudaGetSymbolAddress((void**)&lg_,  g_logits);
    cudaGetSymbolAddress((void**)&bi_,  g_bias);

    // 1. LayerNorm msa -> m
    ln_msa_kernel<<<NL, 256>>>(msa, ln_msa_g, ln_msa_b, m_);

    dim3 gproj(2, NL/128);   // (256/128, 98304/128)

    // 2. ksw = m @ Wk_sw + bk_sw  (into g_o as temp)
    gemm256_kernel<false,false,true,false><<<gproj, 256>>>(m_, nullptr, Wk_sw, bk_sw, nullptr, 1.f, o_);
    // 3. q_sw = (m[n=0] @ Wq_sw + bq_sw) * scale
    gemm256_kernel<false,false,true,false><<<dim3(2,3), 256>>>(m_, nullptr, Wq_sw, bq_sw, nullptr, SCALE, qsw_);
    // 4. sw_logits
    swlogits_kernel<<<NL, 256>>>(qsw_, o_, sw_);
    // 5. softmax over n -> seq_weight
    swsoftmax_kernel<<<Ll*Hh, 256>>>(sw_);
    // 6. q = (m @ Wq) * seq_weight   (fused epilogue)
    gemm256_kernel<false,false,false,true><<<gproj, 256>>>(m_, nullptr, Wq, nullptr, sw_, 1.f, q_);
    // 7. k = (m @ Wk) * scale
    gemm256_kernel<false,false,false,false><<<gproj, 256>>>(m_, nullptr, Wk, nullptr, nullptr, SCALE, k_);
    // 8. v = m @ Wv
    gemm256_kernel<false,false,false,false><<<gproj, 256>>>(m_, nullptr, Wv, nullptr, nullptr, 1.f, v_);
    // 9. gate = sigmoid(m @ Wg + bg)
    gemm256_kernel<false,true,true,false><<<gproj, 256>>>(m_, nullptr, Wg, bg, nullptr, 1.f, gg_);
    // 10. pair bias = LN(pair) @ Wb
    pairbias_kernel<<<LLp, 128>>>(pair, ln_pair_g, ln_pair_b, Wb, bi_);
    // 11. logits per head (+bias fused)
    logits_kernel<<<dim3(Ll/64, Ll/64, Hh), 256>>>(q_, k_, bi_, lg_);
    // 12. attn = softmax(logits) over j
    attnsoftmax_kernel<<<Hh*Ll, Ll>>>(lg_);
    // 13. out = attn @ v  (into g_o)
    outgemm_kernel<<<dim3((Nn*DHh)/64, Ll/64, Hh), 256>>>(lg_, v_, o_);
    // 14. y = (out * gate) @ Wo + bo
    gemm256_kernel<true,false,true,false><<<gproj, 256>>>(o_, gg_, Wo, bo, nullptr, 1.f, out);
}

// round 5
// speedup vs baseline: 1.9425x; 1.9425x over previous
#include <cuda_runtime.h>
#include <math.h>
#include <stdint.h>

// Problem constants
#define Nn   256
#define Ll   384
#define Dd   256
#define DP   128
#define Hh   8
#define DHh  32
#define NL   (Nn*Ll)      // 98304 rows
#define LLp  (Ll*Ll)      // 147456
#define EPSF 1e-5f
#define SCALE 0.17677669529663687f  // 1/sqrt(32)

// ---------------- scratch (device globals; no allocation allowed) ----------------
__device__ float g_m   [NL*Dd];   // layernormed msa
__device__ float g_q   [NL*Dd];   // q projection (seq-weighted in epilogue)
__device__ float g_k   [NL*Dd];   // k projection (scaled)
__device__ float g_v   [NL*Dd];   // v projection
__device__ float g_g   [NL*Dd];   // gate
__device__ float g_o   [NL*Dd];   // ksw temp, later attention output
__device__ float g_qsw [Ll*Dd];   // seq-weight queries
__device__ float g_sw  [NL*Hh];   // sw logits -> seq weights
__device__ float g_logits[Hh*LLp]; // logits(+bias) -> attn
__device__ float g_bias  [Hh*LLp]; // pair bias

// ---------------- tf32 helpers ----------------
__device__ __forceinline__ uint32_t f2tf32(float f) {
    uint32_t r;
    asm("cvt.rna.tf32.f32 %0, %1;" : "=r"(r) : "f"(f));
    return r;
}

__device__ __forceinline__ void mma_tf32(float& c0, float& c1, float& c2, float& c3,
                                         uint32_t a0, uint32_t a1, uint32_t a2, uint32_t a3,
                                         uint32_t b0, uint32_t b1) {
    asm volatile("mma.sync.aligned.m16n8k8.row.col.f32.tf32.tf32.f32 "
                 "{%0,%1,%2,%3}, {%4,%5,%6,%7}, {%8,%9}, {%0,%1,%2,%3};"
                 : "+f"(c0), "+f"(c1), "+f"(c2), "+f"(c3)
                 : "r"(a0), "r"(a1), "r"(a2), "r"(a3), "r"(b0), "r"(b1));
}

// ---------------- LayerNorm over D=256 (one row per block) ----------------
__global__ void ln_msa_kernel(const float* __restrict__ x, const float* __restrict__ g,
                              const float* __restrict__ b, float* __restrict__ out) {
    __shared__ float s1[8], s2[8];
    __shared__ float mu_s, rs_s;
    int row = blockIdx.x;
    int t = threadIdx.x;
    float v = x[(size_t)row*Dd + t];
    float s = v, q = v*v;
    #pragma unroll
    for (int o = 16; o; o >>= 1) {
        s += __shfl_down_sync(0xffffffffu, s, o);
        q += __shfl_down_sync(0xffffffffu, q, o);
    }
    int lane = t & 31, w = t >> 5;
    if (!lane) { s1[w] = s; s2[w] = q; }
    __syncthreads();
    if (w == 0) {
        float ss = (lane < 8) ? s1[lane] : 0.f;
        float qq = (lane < 8) ? s2[lane] : 0.f;
        #pragma unroll
        for (int o = 16; o; o >>= 1) {
            ss += __shfl_down_sync(0xffffffffu, ss, o);
            qq += __shfl_down_sync(0xffffffffu, qq, o);
        }
        if (!lane) {
            float mu = ss * (1.0f/Dd);
            float var = qq * (1.0f/Dd) - mu*mu;
            mu_s = mu;
            rs_s = rsqrtf(var + EPSF);
        }
    }
    __syncthreads();
    out[(size_t)row*Dd + t] = (v - mu_s) * rs_s * g[t] + b[t];
}

// ============================================================================
// TF32 GEMM: C[Mx256] = act((A(*A2) @ W + bias)*scale [*sw])
// A: Mx256 row-major, W: 256x256 row-major.
// BM=128, BN=128, BK=32, 256 threads (8 warps, 4x2), warp tile 32x64.
// mma.sync m16n8k8 tf32.
// ============================================================================
template<bool GATE, bool SIG, bool BIAS, bool SW>
__global__ void __launch_bounds__(256) gemm256_tf32(
        const float* __restrict__ A, const float* __restrict__ A2,
        const float* __restrict__ W, const float* __restrict__ bias,
        const float* __restrict__ swp,
        float scale, float* __restrict__ C) {
    __shared__ uint32_t As[128][36];   // [m][k], pad 4
    __shared__ uint32_t Bs[32][132];   // [k][n], pad 4
    int tid = threadIdx.x;
    int wid = tid >> 5, lane = tid & 31;
    int gid = lane >> 2, tig = lane & 3;
    int wm0 = (wid >> 1) * 32;         // warp m offset (0,32,64,96)
    int wn0 = (wid & 1) * 64;          // warp n offset (0,64)
    int m0 = blockIdx.y * 128, n0 = blockIdx.x * 128;

    float acc[2][8][4];
    #pragma unroll
    for (int mf = 0; mf < 2; mf++)
        #pragma unroll
        for (int nf = 0; nf < 8; nf++)
            #pragma unroll
            for (int e = 0; e < 4; e++) acc[mf][nf][e] = 0.f;

    for (int kt = 0; kt < 8; kt++) {
        int k0 = kt * 32;
        // load A tile 128x32
        #pragma unroll
        for (int u = 0; u < 4; u++) {
            int f = tid + u*256;
            int row = f >> 3, c4 = f & 7;
            const float* ap = A + (size_t)(m0+row)*Dd + k0 + c4*4;
            float4 v = *(const float4*)ap;
            if (GATE) {
                const float* gp = A2 + (size_t)(m0+row)*Dd + k0 + c4*4;
                float4 gt = *(const float4*)gp;
                v.x *= gt.x; v.y *= gt.y; v.z *= gt.z; v.w *= gt.w;
            }
            uint4 tv;
            tv.x = f2tf32(v.x); tv.y = f2tf32(v.y);
            tv.z = f2tf32(v.z); tv.w = f2tf32(v.w);
            *(uint4*)&As[row][c4*4] = tv;
        }
        // load W tile 32x128
        #pragma unroll
        for (int u = 0; u < 4; u++) {
            int f = tid + u*256;
            int kr = f >> 5, c4 = f & 31;
            float4 v = *(const float4*)(W + (size_t)(k0+kr)*Dd + n0 + c4*4);
            uint4 tv;
            tv.x = f2tf32(v.x); tv.y = f2tf32(v.y);
            tv.z = f2tf32(v.z); tv.w = f2tf32(v.w);
            *(uint4*)&Bs[kr][c4*4] = tv;
        }
        __syncthreads();
        #pragma unroll
        for (int kk = 0; kk < 4; kk++) {
            int kb = kk * 8;
            uint32_t a[2][4];
            #pragma unroll
            for (int mf = 0; mf < 2; mf++) {
                int r = wm0 + mf*16 + gid;
                a[mf][0] = As[r][kb + tig];
                a[mf][1] = As[r+8][kb + tig];
                a[mf][2] = As[r][kb + tig + 4];
                a[mf][3] = As[r+8][kb + tig + 4];
            }
            uint32_t b[8][2];
            #pragma unroll
            for (int nf = 0; nf < 8; nf++) {
                int cn = wn0 + nf*8 + gid;
                b[nf][0] = Bs[kb + tig][cn];
                b[nf][1] = Bs[kb + tig + 4][cn];
            }
            #pragma unroll
            for (int mf = 0; mf < 2; mf++)
                #pragma unroll
                for (int nf = 0; nf < 8; nf++)
                    mma_tf32(acc[mf][nf][0], acc[mf][nf][1], acc[mf][nf][2], acc[mf][nf][3],
                             a[mf][0], a[mf][1], a[mf][2], a[mf][3],
                             b[nf][0], b[nf][1]);
        }
        __syncthreads();
    }
    // epilogue
    #pragma unroll
    for (int mf = 0; mf < 2; mf++) {
        #pragma unroll
        for (int half = 0; half < 2; half++) {
            int row = m0 + wm0 + mf*16 + gid + half*8;
            #pragma unroll
            for (int nf = 0; nf < 8; nf++) {
                int col = n0 + wn0 + nf*8 + tig*2;
                float v0 = acc[mf][nf][half*2 + 0];
                float v1 = acc[mf][nf][half*2 + 1];
                if (BIAS) { v0 += bias[col]; v1 += bias[col+1]; }
                v0 *= scale; v1 *= scale;
                if (SIG) {
                    v0 = 1.f / (1.f + expf(-v0));
                    v1 = 1.f / (1.f + expf(-v1));
                }
                if (SW) {
                    float swv = swp[(size_t)row*Hh + (col >> 5)];  // col even -> same head for pair
                    v0 *= swv; v1 *= swv;
                }
                float2 o; o.x = v0; o.y = v1;
                *(float2*)(C + (size_t)row*Dd + col) = o;
            }
        }
    }
}

// ---------------- sw_logits[n,i,h] = dot(qsw[i,h,:], ksw[n,i,h,:]) ----------------
__global__ void swlogits_kernel(const float* __restrict__ qsw, const float* __restrict__ ksw,
                                float* __restrict__ swout) {
    int row = blockIdx.x;            // n*L + i
    int i = row % Ll;
    int t = threadIdx.x;             // 256: warp w = head
    float v = qsw[i*Dd + t] * ksw[(size_t)row*Dd + t];
    #pragma unroll
    for (int o = 16; o; o >>= 1) v += __shfl_down_sync(0xffffffffu, v, o);
    if ((t & 31) == 0) swout[row*Hh + (t >> 5)] = v;
}

// ---------------- softmax over n (256) for each (i,h) ----------------
__global__ void swsoftmax_kernel(float* __restrict__ sw) {
    __shared__ float sm[8];
    __shared__ float red;
    int ih = blockIdx.x;             // i*H + h
    int n = threadIdx.x;             // 256
    int lane = n & 31, w = n >> 5;
    float v = sw[(size_t)n*(Ll*Hh) + ih];
    float mx = v;
    #pragma unroll
    for (int o = 16; o; o >>= 1) mx = fmaxf(mx, __shfl_down_sync(0xffffffffu, mx, o));
    if (!lane) sm[w] = mx;
    __syncthreads();
    if (w == 0) {
        float x = (lane < 8) ? sm[lane] : -3.4e38f;
        #pragma unroll
        for (int o = 16; o; o >>= 1) x = fmaxf(x, __shfl_down_sync(0xffffffffu, x, o));
        if (!lane) red = x;
    }
    __syncthreads();
    mx = red;
    float e = expf(v - mx);
    float s = e;
    #pragma unroll
    for (int o = 16; o; o >>= 1) s += __shfl_down_sync(0xffffffffu, s, o);
    __syncthreads();
    if (!lane) sm[w] = s;
    __syncthreads();
    if (w == 0) {
        float x = (lane < 8) ? sm[lane] : 0.f;
        #pragma unroll
        for (int o = 16; o; o >>= 1) x += __shfl_down_sync(0xffffffffu, x, o);
        if (!lane) red = x;
    }
    __syncthreads();
    sw[(size_t)n*(Ll*Hh) + ih] = e / red;
}

// ---------------- pair bias: LN(pair row) @ Wb -> bias[h][i][j] ----------------
__global__ void pairbias_kernel(const float* __restrict__ pair, const float* __restrict__ g,
                                const float* __restrict__ b, const float* __restrict__ Wb,
                                float* __restrict__ bias) {
    __shared__ float s1[4], s2[4];
    __shared__ float hp[4][8];
    int ij = blockIdx.x;             // i*L + j
    int t = threadIdx.x;             // 128
    int lane = t & 31, w = t >> 5;
    float v = pair[(size_t)ij*DP + t];
    float s = v, q = v*v;
    #pragma unroll
    for (int o = 16; o; o >>= 1) {
        s += __shfl_down_sync(0xffffffffu, s, o);
        q += __shfl_down_sync(0xffffffffu, q, o);
    }
    if (!lane) { s1[w] = s; s2[w] = q; }
    __syncthreads();
    if (w == 0) {
        float ss = (lane < 4) ? s1[lane] : 0.f;
        float qq = (lane < 4) ? s2[lane] : 0.f;
        #pragma unroll
        for (int o = 16; o; o >>= 1) {
            ss += __shfl_down_sync(0xffffffffu, ss, o);
            qq += __shfl_down_sync(0xffffffffu, qq, o);
        }
        if (!lane) { s1[0] = ss; s2[0] = qq; }
    }
    __syncthreads();
    float mu = s1[0] * (1.0f/DP);
    float var = s2[0] * (1.0f/DP) - mu*mu;
    float ln = (v - mu) * rsqrtf(var + EPSF) * g[t] + b[t];
    float p[8];
    #pragma unroll
    for (int h = 0; h < 8; h++) p[h] = ln * Wb[t*Hh + h];
    #pragma unroll
    for (int h = 0; h < 8; h++)
        #pragma unroll
        for (int o = 16; o; o >>= 1) p[h] += __shfl_down_sync(0xffffffffu, p[h], o);
    if (!lane) {
        #pragma unroll
        for (int h = 0; h < 8; h++) hp[w][h] = p[h];
    }
    __syncthreads();
    if (t < 8) {
        float x = hp[0][t] + hp[1][t] + hp[2][t] + hp[3][t];
        bias[(size_t)t*LLp + ij] = x;
    }
}

// ============================================================================
// TF32 logits: logits[h][i][j] = sum_{n,d} q[n,i,h,d]*k[n,j,h,d] + bias[h][i][j]
// grid (6, 6, 8), 128 threads (4 warps 2x2), BM=BN=64, BK=32 per n-step.
// ============================================================================
__global__ void __launch_bounds__(128) logits_tf32(const float* __restrict__ q,
        const float* __restrict__ kk_, const float* __restrict__ bias,
        float* __restrict__ out) {
    __shared__ uint32_t As[64][36];    // [i][d]
    __shared__ uint32_t Bs[32][68];    // [d][j]
    int h = blockIdx.z;
    int i0 = blockIdx.y * 64, j0 = blockIdx.x * 64;
    int tid = threadIdx.x;
    int wid = tid >> 5, lane = tid & 31;
    int gid = lane >> 2, tig = lane & 3;
    int wm0 = (wid >> 1) * 32;
    int wn0 = (wid & 1) * 32;

    float acc[2][4][4];
    #pragma unroll
    for (int mf = 0; mf < 2; mf++)
        #pragma unroll
        for (int nf = 0; nf < 4; nf++)
            #pragma unroll
            for (int e = 0; e < 4; e++) acc[mf][nf][e] = 0.f;

    for (int n = 0; n < Nn; n++) {
        #pragma unroll
        for (int u = 0; u < 4; u++) {
            int f = tid + u*128;
            int row = f >> 3, c4 = f & 7;
            // A: q rows (i), 32 d's contiguous
            float4 a = *(const float4*)(q + (size_t)(n*Ll + i0 + row)*Dd + h*DHh + c4*4);
            uint4 ta;
            ta.x = f2tf32(a.x); ta.y = f2tf32(a.y);
            ta.z = f2tf32(a.z); ta.w = f2tf32(a.w);
            *(uint4*)&As[row][c4*4] = ta;
            // B: k rows (j), transpose into Bs[d][j]
            float4 bv = *(const float4*)(kk_ + (size_t)(n*Ll + j0 + row)*Dd + h*DHh + c4*4);
            Bs[c4*4+0][row] = f2tf32(bv.x);
            Bs[c4*4+1][row] = f2tf32(bv.y);
            Bs[c4*4+2][row] = f2tf32(bv.z);
            Bs[c4*4+3][row] = f2tf32(bv.w);
        }
        __syncthreads();
        #pragma unroll
        for (int kkk = 0; kkk < 4; kkk++) {
            int kb = kkk * 8;
            uint32_t a[2][4];
            #pragma unroll
            for (int mf = 0; mf < 2; mf++) {
                int r = wm0 + mf*16 + gid;
                a[mf][0] = As[r][kb + tig];
                a[mf][1] = As[r+8][kb + tig];
                a[mf][2] = As[r][kb + tig + 4];
                a[mf][3] = As[r+8][kb + tig + 4];
            }
            uint32_t b[4][2];
            #pragma unroll
            for (int nf = 0; nf < 4; nf++) {
                int cn = wn0 + nf*8 + gid;
                b[nf][0] = Bs[kb + tig][cn];
                b[nf][1] = Bs[kb + tig + 4][cn];
            }
            #pragma unroll
            for (int mf = 0; mf < 2; mf++)
                #pragma unroll
                for (int nf = 0; nf < 4; nf++)
                    mma_tf32(acc[mf][nf][0], acc[mf][nf][1], acc[mf][nf][2], acc[mf][nf][3],
                             a[mf][0], a[mf][1], a[mf][2], a[mf][3],
                             b[nf][0], b[nf][1]);
        }
        __syncthreads();
    }
    #pragma unroll
    for (int mf = 0; mf < 2; mf++) {
        #pragma unroll
        for (int half = 0; half < 2; half++) {
            int i = i0 + wm0 + mf*16 + gid + half*8;
            #pragma unroll
            for (int nf = 0; nf < 4; nf++) {
                int j = j0 + wn0 + nf*8 + tig*2;
                size_t idx = (size_t)h*LLp + (size_t)i*Ll + j;
                float2 bb = *(const float2*)(bias + idx);
                float2 o;
                o.x = acc[mf][nf][half*2 + 0] + bb.x;
                o.y = acc[mf][nf][half*2 + 1] + bb.y;
                *(float2*)(out + idx) = o;
            }
        }
    }
}

// ---------------- softmax over j (384) for each (h, i) ----------------
__global__ void attnsoftmax_kernel(float* __restrict__ logits) {
    __shared__ float sm[12];
    __shared__ float red;
    int hi = blockIdx.x;             // h*L + i
    size_t base = (size_t)hi * Ll;   // == h*LL + i*L
    int j = threadIdx.x;             // 384 threads, 12 warps
    int lane = j & 31, w = j >> 5;
    float v = logits[base + j];
    float mx = v;
    #pragma unroll
    for (int o = 16; o; o >>= 1) mx = fmaxf(mx, __shfl_down_sync(0xffffffffu, mx, o));
    if (!lane) sm[w] = mx;
    __syncthreads();
    if (w == 0) {
        float x = (lane < 12) ? sm[lane] : -3.4e38f;
        #pragma unroll
        for (int o = 16; o; o >>= 1) x = fmaxf(x, __shfl_down_sync(0xffffffffu, x, o));
        if (!lane) red = x;
    }
    __syncthreads();
    mx = red;
    float e = expf(v - mx);
    float s = e;
    #pragma unroll
    for (int o = 16; o; o >>= 1) s += __shfl_down_sync(0xffffffffu, s, o);
    __syncthreads();
    if (!lane) sm[w] = s;
    __syncthreads();
    if (w == 0) {
        float x = (lane < 12) ? sm[lane] : 0.f;
        #pragma unroll
        for (int o = 16; o; o >>= 1) x += __shfl_down_sync(0xffffffffu, x, o);
        if (!lane) red = x;
    }
    __syncthreads();
    logits[base + j] = e / red;
}

// ============================================================================
// TF32 attn@V: out[(n,i),(h,d)] = sum_j attn[h][i][j] * v[(n,j),(h,d)]
// grid (128, 6, 8), 128 threads (4 warps 2x2), BM=64 (i), BN=64 (c=n_l*32+d), BK=32 (j)
// ============================================================================
__global__ void __launch_bounds__(128) outgemm_tf32(const float* __restrict__ attn,
        const float* __restrict__ v, float* __restrict__ out) {
    __shared__ uint32_t As[64][36];    // [i][j]
    __shared__ uint32_t Bs[32][68];    // [j][c]
    int h = blockIdx.z;
    int i0 = blockIdx.y * 64, c0 = blockIdx.x * 64;
    int tid = threadIdx.x;
    int wid = tid >> 5, lane = tid & 31;
    int gid = lane >> 2, tig = lane & 3;
    int wm0 = (wid >> 1) * 32;
    int wn0 = (wid & 1) * 32;

    float acc[2][4][4];
    #pragma unroll
    for (int mf = 0; mf < 2; mf++)
        #pragma unroll
        for (int nf = 0; nf < 4; nf++)
            #pragma unroll
            for (int e = 0; e < 4; e++) acc[mf][nf][e] = 0.f;

    for (int jt = 0; jt < 12; jt++) {
        int j0 = jt * 32;
        #pragma unroll
        for (int u = 0; u < 4; u++) {
            int f = tid + u*128;
            {   // attn tile 64 i x 32 j (natural layout)
                int row = f >> 3, c4 = f & 7;
                float4 a = *(const float4*)(attn + (size_t)h*LLp + (size_t)(i0 + row)*Ll + j0 + c4*4);
                uint4 ta;
                ta.x = f2tf32(a.x); ta.y = f2tf32(a.y);
                ta.z = f2tf32(a.z); ta.w = f2tf32(a.w);
                *(uint4*)&As[row][c4*4] = ta;
            }
            {   // v tile 32 j x 64 c (natural layout)
                int jrow = f >> 4, cc = f & 15;
                int cg = c0 + cc*4;
                int nn = cg >> 5, dd = cg & 31;
                float4 bv = *(const float4*)(v + (size_t)(nn*Ll + j0 + jrow)*Dd + h*DHh + dd);
                uint4 tb;
                tb.x = f2tf32(bv.x); tb.y = f2tf32(bv.y);
                tb.z = f2tf32(bv.z); tb.w = f2tf32(bv.w);
                *(uint4*)&Bs[jrow][cc*4] = tb;
            }
        }
        __syncthreads();
        #pragma unroll
        for (int kkk = 0; kkk < 4; kkk++) {
            int kb = kkk * 8;
            uint32_t a[2][4];
            #pragma unroll
            for (int mf = 0; mf < 2; mf++) {
                int r = wm0 + mf*16 + gid;
                a[mf][0] = As[r][kb + tig];
                a[mf][1] = As[r+8][kb + tig];
                a[mf][2] = As[r][kb + tig + 4];
                a[mf][3] = As[r+8][kb + tig + 4];
            }
            uint32_t b[4][2];
            #pragma unroll
            for (int nf = 0; nf < 4; nf++) {
                int cn = wn0 + nf*8 + gid;
                b[nf][0] = Bs[kb + tig][cn];
                b[nf][1] = Bs[kb + tig + 4][cn];
            }
            #pragma unroll
            for (int mf = 0; mf < 2; mf++)
                #pragma unroll
                for (int nf = 0; nf < 4; nf++)
                    mma_tf32(acc[mf][nf][0], acc[mf][nf][1], acc[mf][nf][2], acc[mf][nf][3],
                             a[mf][0], a[mf][1], a[mf][2], a[mf][3],
                             b[nf][0], b[nf][1]);
        }
        __syncthreads();
    }
    #pragma unroll
    for (int mf = 0; mf < 2; mf++) {
        #pragma unroll
        for (int half = 0; half < 2; half++) {
            int i = i0 + wm0 + mf*16 + gid + half*8;
            #pragma unroll
            for (int nf = 0; nf < 4; nf++) {
                int cg = c0 + wn0 + nf*8 + tig*2;
                int nn = cg >> 5, dd = cg & 31;
                float2 o;
                o.x = acc[mf][nf][half*2 + 0];
                o.y = acc[mf][nf][half*2 + 1];
                *(float2*)(out + (size_t)(nn*Ll + i)*Dd + h*DHh + dd) = o;
            }
        }
    }
}

// ---------------- host launch ----------------
extern "C" void kernel_launch(void* const* d_in, const int* in_sizes, int n_in,
                              void* d_out, int out_size) {
    const float* msa       = (const float*)d_in[0];
    const float* pair      = (const float*)d_in[1];
    const float* ln_msa_g  = (const float*)d_in[2];
    const float* ln_msa_b  = (const float*)d_in[3];
    const float* ln_pair_g = (const float*)d_in[4];
    const float* ln_pair_b = (const float*)d_in[5];
    const float* Wq_sw     = (const float*)d_in[6];
    const float* bq_sw     = (const float*)d_in[7];
    const float* Wk_sw     = (const float*)d_in[8];
    const float* bk_sw     = (const float*)d_in[9];
    const float* Wq        = (const float*)d_in[10];
    const float* Wk        = (const float*)d_in[11];
    const float* Wv        = (const float*)d_in[12];
    const float* Wb        = (const float*)d_in[13];
    const float* Wg        = (const float*)d_in[14];
    const float* bg        = (const float*)d_in[15];
    const float* Wo        = (const float*)d_in[16];
    const float* bo        = (const float*)d_in[17];
    float* out = (float*)d_out;

    float *m_, *q_, *k_, *v_, *gg_, *o_, *qsw_, *sw_, *lg_, *bi_;
    cudaGetSymbolAddress((void**)&m_,   g_m);
    cudaGetSymbolAddress((void**)&q_,   g_q);
    cudaGetSymbolAddress((void**)&k_,   g_k);
    cudaGetSymbolAddress((void**)&v_,   g_v);
    cudaGetSymbolAddress((void**)&gg_,  g_g);
    cudaGetSymbolAddress((void**)&o_,   g_o);
    cudaGetSymbolAddress((void**)&qsw_, g_qsw);
    cudaGetSymbolAddress((void**)&sw_,  g_sw);
    cudaGetSymbolAddress((void**)&lg_,  g_logits);
    cudaGetSymbolAddress((void**)&bi_,  g_bias);

    // 1. LayerNorm msa -> m
    ln_msa_kernel<<<NL, 256>>>(msa, ln_msa_g, ln_msa_b, m_);

    dim3 gproj(2, NL/128);   // (256/128, 98304/128)

    // 2. ksw = m @ Wk_sw + bk_sw  (into g_o as temp)
    gemm256_tf32<false,false,true,false><<<gproj, 256>>>(m_, nullptr, Wk_sw, bk_sw, nullptr, 1.f, o_);
    // 3. q_sw = (m[n=0] @ Wq_sw + bq_sw) * scale
    gemm256_tf32<false,false,true,false><<<dim3(2,3), 256>>>(m_, nullptr, Wq_sw, bq_sw, nullptr, SCALE, qsw_);
    // 4. sw_logits
    swlogits_kernel<<<NL, 256>>>(qsw_, o_, sw_);
    // 5. softmax over n -> seq_weight
    swsoftmax_kernel<<<Ll*Hh, 256>>>(sw_);
    // 6. q = (m @ Wq) * seq_weight   (fused epilogue)
    gemm256_tf32<false,false,false,true><<<gproj, 256>>>(m_, nullptr, Wq, nullptr, sw_, 1.f, q_);
    // 7. k = (m @ Wk) * scale
    gemm256_tf32<false,false,false,false><<<gproj, 256>>>(m_, nullptr, Wk, nullptr, nullptr, SCALE, k_);
    // 8. v = m @ Wv
    gemm256_tf32<false,false,false,false><<<gproj, 256>>>(m_, nullptr, Wv, nullptr, nullptr, 1.f, v_);
    // 9. gate = sigmoid(m @ Wg + bg)
    gemm256_tf32<false,true,true,false><<<gproj, 256>>>(m_, nullptr, Wg, bg, nullptr, 1.f, gg_);
    // 10. pair bias = LN(pair) @ Wb
    pairbias_kernel<<<LLp, 128>>>(pair, ln_pair_g, ln_pair_b, Wb, bi_);
    // 11. logits per head (+bias fused)
    logits_tf32<<<dim3(Ll/64, Ll/64, Hh), 128>>>(q_, k_, bi_, lg_);
    // 12. attn = softmax(logits) over j
    attnsoftmax_kernel<<<Hh*Ll, Ll>>>(lg_);
    // 13. out = attn @ v  (into g_o)
    outgemm_tf32<<<dim3((Nn*DHh)/64, Ll/64, Hh), 128>>>(lg_, v_, o_);
    // 14. y = (out * gate) @ Wo + bo
    gemm256_tf32<true,false,true,false><<<gproj, 256>>>(o_, gg_, Wo, bo, nullptr, 1.f, out);
}